// round 1
// baseline (speedup 1.0000x reference)
#include <cuda_runtime.h>
#include <cstdint>

// CRF NLL:  out[b] = logZ[b] - score_sentence[b]
// B=512, S=1024, T=48. Forward scan done in linear domain:
//   p_{k} = (E @ p_{k-1}) .* exp(emit_k) * 2^{-lc2_{k-1}},  E = exp(trans)
// with running log2 normalizer accumulated in double.

static constexpr int T_ = 48;
static constexpr int S_ = 1024;
static constexpr int START_ = 45;
static constexpr int STOP_ = 46;
static constexpr float LOG2E_ = 1.4426950408889634f;

__device__ int g_len[2048];

__device__ __forceinline__ float ex2f_(float x) {
    float y; asm("ex2.approx.ftz.f32 %0, %1;" : "=f"(y) : "f"(x)); return y;
}
__device__ __forceinline__ float lg2f_(float x) {
    float y; asm("lg2.approx.f32 %0, %1;" : "=f"(y) : "f"(x)); return y;
}
__device__ __forceinline__ unsigned long long pack2_(float lo, float hi) {
    unsigned long long r; asm("mov.b64 %0, {%1,%2};" : "=l"(r) : "f"(lo), "f"(hi)); return r;
}
__device__ __forceinline__ void fma2_(unsigned long long& acc, unsigned long long a, unsigned long long b) {
    // packed f32x2 FMA: acc = a*b + acc (two fp32 lanes per instruction)
    asm("fma.rn.f32x2 %0, %1, %2, %0;" : "+l"(acc) : "l"(a), "l"(b));
}
__device__ __forceinline__ void unpack2_(unsigned long long v, float& lo, float& hi) {
    asm("mov.b64 {%0,%1}, %2;" : "=f"(lo), "=f"(hi) : "l"(v));
}

// ---------------------------------------------------------------------------
// Kernel 1: score_sentence per batch + sequence length. Writes score into out[b]
// (kernel 2 later does out[b] = logZ - out[b]). Fully overwrites out each run.
// ---------------------------------------------------------------------------
__global__ void score_sent_kernel(const float* __restrict__ feats,
                                  const float* __restrict__ masks,
                                  const int* __restrict__ tags,
                                  const float* __restrict__ trans,
                                  float* __restrict__ out) {
    __shared__ float st[T_ * T_];
    __shared__ float rs[8];
    __shared__ int   rc[8];

    const int b   = blockIdx.x;
    const int tid = threadIdx.x;

    for (int i = tid; i < T_ * T_; i += blockDim.x) st[i] = trans[i];
    __syncthreads();

    const float* mrow = masks + (size_t)b * S_;
    const int*   trow = tags  + (size_t)b * S_;
    const float* frow = feats + (size_t)b * S_ * T_;

    float sum = 0.0f;
    int   cnt = 0;
    for (int s = tid; s < S_; s += blockDim.x) {
        if (mrow[s] != 0.0f) {
            cnt++;
            int tg = trow[s];
            int tp = (s == 0) ? START_ : trow[s - 1];
            sum += frow[s * T_ + tg] + st[tg * T_ + tp];
        }
    }
    #pragma unroll
    for (int o = 16; o > 0; o >>= 1) {
        sum += __shfl_xor_sync(0xffffffffu, sum, o);
        cnt += __shfl_xor_sync(0xffffffffu, cnt, o);
    }
    const int w = tid >> 5;
    if ((tid & 31) == 0) { rs[w] = sum; rc[w] = cnt; }
    __syncthreads();
    if (tid == 0) {
        float tot = 0.0f;
        int   len = 0;
        const int nw = blockDim.x >> 5;
        for (int i = 0; i < nw; i++) { tot += rs[i]; len += rc[i]; }
        int last = trow[len - 1];            // len >= 1 by construction
        tot += st[STOP_ * T_ + last];
        out[b]   = tot;
        g_len[b] = len;
    }
}

// ---------------------------------------------------------------------------
// Kernel 2: forward scan, one warp per batch. Lane owns tags (lane) and
// (lane+32, if lane<16). E rows packed as f32x2 pairs in registers.
// p vector double-buffered in shared, read as 16B broadcasts.
// ---------------------------------------------------------------------------
__global__ void __launch_bounds__(128, 1)
crf_scan_kernel(const float* __restrict__ feats,
                const float* __restrict__ trans,
                float* __restrict__ out,
                int Btot) {
    __shared__ float4 pbuf[4][2][12];   // [warp][buf][48 floats]

    const int warp = threadIdx.x >> 5;
    const int lane = threadIdx.x & 31;
    const int b = blockIdx.x * 4 + warp;
    if (b >= Btot) return;

    const float* f = feats + (size_t)b * S_ * T_;
    const int len  = g_len[b];

    const int  t0   = lane;
    const int  t1   = lane + 32;
    const bool has1 = (lane < 16);

    // --- Prologue: E rows into packed registers (accurate expf; NEG -> 0) ---
    unsigned long long e0p[24], e1p[24];
    #pragma unroll
    for (int j = 0; j < 24; j++) {
        float a  = expf(trans[t0 * T_ + 2 * j]);
        float bb = expf(trans[t0 * T_ + 2 * j + 1]);
        e0p[j] = pack2_(a, bb);
        float c2 = has1 ? expf(trans[t1 * T_ + 2 * j])     : 0.0f;
        float d2 = has1 ? expf(trans[t1 * T_ + 2 * j + 1]) : 0.0f;
        e1p[j] = pack2_(c2, d2);
    }
    const float es0 = expf(trans[STOP_ * T_ + t0]);
    const float es1 = has1 ? expf(trans[STOP_ * T_ + t1]) : 0.0f;

    // --- init p: delta at START ---
    {
        float* p0 = reinterpret_cast<float*>(&pbuf[warp][0][0]);
        p0[t0] = 0.0f;
        if (has1) p0[t1] = (t1 == START_) ? 1.0f : 0.0f;
    }
    __syncwarp();

    // --- emission prefetch, distance 3 ---
    float emA0, emA1, emA2, emB0, emB1, emB2;
    emA0 = f[t0];
    emB0 = has1 ? f[t1] : 0.0f;
    emA1 = (1 < len) ? f[T_ + t0] : 0.0f;
    emB1 = (1 < len && has1) ? f[T_ + t1] : 0.0f;
    emA2 = (2 < len) ? f[2 * T_ + t0] : 0.0f;
    emB2 = (2 < len && has1) ? f[2 * T_ + t1] : 0.0f;

    float  lc2 = 0.0f;     // log2 of last normalizer (folded into next eE)
    double A   = 0.0;      // accumulated log2 normalizer history
    float  r0  = 0.0f, r1 = 0.0f;

    for (int k = 0; k < len; k++) {
        const ulonglong2* pv =
            reinterpret_cast<const ulonglong2*>(&pbuf[warp][k & 1][0]);

        const float eE0 = ex2f_(fmaf(emA0, LOG2E_, -lc2));
        const float eE1 = ex2f_(fmaf(emB0, LOG2E_, -lc2));

        unsigned long long acc00 = 0ull, acc01 = 0ull;
        unsigned long long acc10 = 0ull, acc11 = 0ull;
        #pragma unroll
        for (int i = 0; i < 12; i++) {
            ulonglong2 v = pv[i];               // 4 p-values, broadcast LDS.128
            fma2_(acc00, e0p[2 * i],     v.x);
            fma2_(acc01, e0p[2 * i + 1], v.y);
            fma2_(acc10, e1p[2 * i],     v.x);
            fma2_(acc11, e1p[2 * i + 1], v.y);
        }
        float a0, a1, b0c, b1c, c0, c1, d0, d1;
        unpack2_(acc00, a0, a1);  unpack2_(acc01, b0c, b1c);
        unpack2_(acc10, c0, c1);  unpack2_(acc11, d0, d1);
        const float dot0 = (a0 + b0c) + (a1 + b1c);
        const float dot1 = (c0 + d0) + (c1 + d1);

        r0 = dot0 * eE0;
        r1 = dot1 * eE1;

        float* pn = reinterpret_cast<float*>(&pbuf[warp][(k & 1) ^ 1][0]);
        pn[t0] = r0;
        if (has1) pn[t1] = r1;

        // scalar renormalizer for next step (off the matvec critical path)
        const float c = __shfl_sync(0xffffffffu, r0, 0);
        A  += (double)lc2;
        lc2 = lg2f_(c);

        // rotate emission prefetch
        emA0 = emA1; emA1 = emA2;
        emB0 = emB1; emB1 = emB2;
        const int  kp = k + 3;
        const bool ld = (kp < len);
        emA2 = ld ? f[(size_t)kp * T_ + t0] : 0.0f;
        emB2 = (ld && has1) ? f[(size_t)kp * T_ + t1] : 0.0f;

        __syncwarp();
    }

    // --- final: logZ = ln2 * (A + log2( sum_t p_L[t] * exp(trans[STOP,t]) )) ---
    float part = r0 * es0 + (has1 ? r1 * es1 : 0.0f);
    #pragma unroll
    for (int o = 16; o > 0; o >>= 1) part += __shfl_xor_sync(0xffffffffu, part, o);

    if (lane == 0) {
        double lz2  = A + (double)lg2f_(part);
        float  logZ = (float)(lz2 * 0.693147180559945309);
        out[b] = logZ - out[b];
    }
}

// ---------------------------------------------------------------------------
extern "C" void kernel_launch(void* const* d_in, const int* in_sizes, int n_in,
                              void* d_out, int out_size) {
    const float* feats = (const float*)d_in[0];
    const float* masks = (const float*)d_in[1];
    const int*   tags  = (const int*)d_in[2];
    const float* trans = (const float*)d_in[3];
    float* out = (float*)d_out;
    const int B = out_size;                 // 512

    score_sent_kernel<<<B, 256>>>(feats, masks, tags, trans, out);
    crf_scan_kernel<<<(B + 3) / 4, 128>>>(feats, trans, out, B);
}